// round 4
// baseline (speedup 1.0000x reference)
#include <cuda_runtime.h>
#include <math.h>

#define BGRAPH 64
#define NNODE  1024
#define FDIM   128
#define NUM    (BGRAPH*NNODE)
#define NE     2097152
#define KSEL   4

__device__ float d_xn  [NUM*FDIM];
__device__ float d_hf  [NUM*FDIM];
__device__ float d_hs  [NUM*FDIM];
__device__ float d_feat[NUM*FDIM];
__device__ float d_stru[NUM*FDIM];
__device__ float d_gate[NUM*FDIM];
__device__ int   d_topk[NUM*KSEL];
__device__ int   d_cntf[NUM];
__device__ int   d_cnts[NUM];
__device__ int   d_offf[NUM];
__device__ int   d_offs[NUM];
__device__ int   d_fillf[NUM];
__device__ int   d_fills[NUM];
__device__ float d_dinvf[NUM];
__device__ float d_dinvs[NUM];
__device__ int   d_csrf[NUM*KSEL];
__device__ int   d_csrs[NE];

__device__ __forceinline__ float warp_sum(float v) {
#pragma unroll
    for (int o = 16; o > 0; o >>= 1) v += __shfl_xor_sync(0xffffffffu, v, o);
    return v;
}

__device__ __forceinline__ void ins4(unsigned long long& k0, unsigned long long& k1,
                                     unsigned long long& k2, unsigned long long& k3,
                                     unsigned long long c) {
    if (c < k3) {
        k3 = c;
        if (k3 < k2) { unsigned long long t = k2; k2 = k3; k3 = t; }
        if (k2 < k1) { unsigned long long t = k1; k1 = k2; k2 = t; }
        if (k1 < k0) { unsigned long long t = k0; k0 = k1; k1 = t; }
    }
}

// 1) row-normalize x
__global__ void knorm(const float* __restrict__ x) {
    int row = blockIdx.x, t = threadIdx.x;
    float v = x[row * FDIM + t];
    float ss = warp_sum(v * v);
    __shared__ float sh[4];
    if ((t & 31) == 0) sh[t >> 5] = ss;
    __syncthreads();
    float tot = sh[0] + sh[1] + sh[2] + sh[3];
    float den = fmaxf(sqrtf(tot), 1e-8f);
    d_xn[row * FDIM + t] = v / den;
}

// 2) zero counters
__global__ void kinit() {
    int i = blockIdx.x * blockDim.x + threadIdx.x;
    if (i < NUM) { d_cntf[i] = 0; d_cnts[i] = 0; d_fillf[i] = 0; d_fills[i] = 0; }
}

// 3) structural in-degree
__global__ void kcnt_s(const int* __restrict__ ei) {
    int e = blockIdx.x * blockDim.x + threadIdx.x;
    if (e < NE) atomicAdd(&d_cnts[ei[NE + e]], 1);
}

// 4) all-pairs cosine + top-4 farthest. grid(16,64), 256 thr; 64 rows x (8x128) cols.
__global__ void __launch_bounds__(256) ktopk() {
    __shared__ __align__(16) float As[32 * 68];
    __shared__ __align__(16) float Bs[32 * 132];
    const int g = blockIdx.y;
    const int rowbase = blockIdx.x * 64;
    const int t = threadIdx.x, tx = t & 15, ty = t >> 4;
    const float* xg = d_xn + (size_t)g * NNODE * FDIM;

    unsigned long long tkA[4], tkB[4], tkC[4], tkD[4];
#pragma unroll
    for (int ri = 0; ri < 4; ri++) { tkA[ri]=tkB[ri]=tkC[ri]=tkD[ri]=0xffffffffffffffffull; }

    for (int cc = 0; cc < 8; cc++) {
        float acc[4][8];
#pragma unroll
        for (int ri = 0; ri < 4; ri++)
#pragma unroll
            for (int ci = 0; ci < 8; ci++) acc[ri][ci] = 0.f;

        for (int kc = 0; kc < 4; kc++) {
            __syncthreads();
#pragma unroll
            for (int j = 0; j < 2; j++) {
                int idx = t + j * 256;
                int r = idx >> 3, k4 = idx & 7;
                float4 v = *(const float4*)&xg[(rowbase + r) * FDIM + kc * 32 + k4 * 4];
                As[(k4 * 4 + 0) * 68 + r] = v.x; As[(k4 * 4 + 1) * 68 + r] = v.y;
                As[(k4 * 4 + 2) * 68 + r] = v.z; As[(k4 * 4 + 3) * 68 + r] = v.w;
            }
#pragma unroll
            for (int j = 0; j < 4; j++) {
                int idx = t + j * 256;
                int c = idx >> 3, k4 = idx & 7;
                float4 v = *(const float4*)&xg[(cc * 128 + c) * FDIM + kc * 32 + k4 * 4];
                Bs[(k4 * 4 + 0) * 132 + c] = v.x; Bs[(k4 * 4 + 1) * 132 + c] = v.y;
                Bs[(k4 * 4 + 2) * 132 + c] = v.z; Bs[(k4 * 4 + 3) * 132 + c] = v.w;
            }
            __syncthreads();
#pragma unroll 8
            for (int k = 0; k < 32; k++) {
                float4 a  = *(const float4*)&As[k * 68 + ty * 4];
                float4 b0 = *(const float4*)&Bs[k * 132 + tx * 8];
                float4 b1 = *(const float4*)&Bs[k * 132 + tx * 8 + 4];
                float av[4] = {a.x, a.y, a.z, a.w};
                float bv[8] = {b0.x, b0.y, b0.z, b0.w, b1.x, b1.y, b1.z, b1.w};
#pragma unroll
                for (int ri = 0; ri < 4; ri++)
#pragma unroll
                    for (int ci = 0; ci < 8; ci++) acc[ri][ci] += av[ri] * bv[ci];
            }
        }
        int cbase = cc * 128 + tx * 8;
#pragma unroll
        for (int ri = 0; ri < 4; ri++)
#pragma unroll
            for (int ci = 0; ci < 8; ci++) {
                float dval = 1.0f - acc[ri][ci];
                unsigned u = __float_as_uint(dval);
                u = (u & 0x80000000u) ? ~u : (u | 0x80000000u);
                unsigned long long key =
                    (((unsigned long long)(~u)) << 10) | (unsigned long long)(cbase + ci);
                ins4(tkA[ri], tkB[ri], tkC[ri], tkD[ri], key);
            }
    }
#pragma unroll
    for (int off = 8; off > 0; off >>= 1) {
#pragma unroll
        for (int ri = 0; ri < 4; ri++) {
            unsigned long long c0 = __shfl_down_sync(0xffffffffu, tkA[ri], off, 16);
            unsigned long long c1 = __shfl_down_sync(0xffffffffu, tkB[ri], off, 16);
            unsigned long long c2 = __shfl_down_sync(0xffffffffu, tkC[ri], off, 16);
            unsigned long long c3 = __shfl_down_sync(0xffffffffu, tkD[ri], off, 16);
            if (tx < off) {
                ins4(tkA[ri], tkB[ri], tkC[ri], tkD[ri], c0);
                ins4(tkA[ri], tkB[ri], tkC[ri], tkD[ri], c1);
                ins4(tkA[ri], tkB[ri], tkC[ri], tkD[ri], c2);
                ins4(tkA[ri], tkB[ri], tkC[ri], tkD[ri], c3);
            }
        }
    }
    if (tx == 0) {
#pragma unroll
        for (int ri = 0; ri < 4; ri++) {
            int grow = g * NNODE + rowbase + ty * 4 + ri;
            unsigned long long ks[4] = {tkA[ri], tkB[ri], tkC[ri], tkD[ri]};
#pragma unroll
            for (int q = 0; q < 4; q++) {
                int j  = (int)(ks[q] & 1023ull);
                int dg = g * NNODE + j;
                d_topk[grow * 4 + q] = dg;
                atomicAdd(&d_cntf[dg], 1);
            }
        }
    }
}

// 5) single-block exclusive scan over 65536 ints
__global__ void kscan(int which) {
    const int* cnt = which ? d_cnts : d_cntf;
    int* off = which ? d_offs : d_offf;
    __shared__ int sh[1024];
    int t = threadIdx.x;
    int base = t * 64;
    int sum = 0;
    for (int i = 0; i < 64; i++) sum += cnt[base + i];
    sh[t] = sum;
    __syncthreads();
    for (int o = 1; o < 1024; o <<= 1) {
        int v = (t >= o) ? sh[t - o] : 0;
        __syncthreads();
        sh[t] += v;
        __syncthreads();
    }
    int run = sh[t] - sum;
    for (int i = 0; i < 64; i++) { int c = cnt[base + i]; off[base + i] = run; run += c; }
}

// 6) dinv = rsqrt(deg) incl. self-loop
__global__ void kdinv() {
    int i = blockIdx.x * blockDim.x + threadIdx.x;
    if (i < NUM) {
        d_dinvf[i] = rsqrtf((float)(d_cntf[i] + 1));
        d_dinvs[i] = rsqrtf((float)(d_cnts[i] + 1));
    }
}

// 7) CSR fill
__global__ void kfill_f() {
    int e = blockIdx.x * blockDim.x + threadIdx.x;
    if (e < NUM * KSEL) {
        int srcn = e >> 2;
        int dg = d_topk[e];
        int pos = d_offf[dg] + atomicAdd(&d_fillf[dg], 1);
        d_csrf[pos] = srcn;
    }
}
__global__ void kfill_s(const int* __restrict__ ei) {
    int e = blockIdx.x * blockDim.x + threadIdx.x;
    if (e < NE) {
        int s = ei[e], dg = ei[NE + e];
        int pos = d_offs[dg] + atomicAdd(&d_fills[dg], 1);
        d_csrs[pos] = s;
    }
}

// 8) h = x @ W (z: 0=feat, 1=stru)
__global__ void __launch_bounds__(256) kgemm_h(const float* __restrict__ x,
                                               const float* __restrict__ Wf,
                                               const float* __restrict__ Wst) {
    const float* W = blockIdx.z ? Wst : Wf;
    float* out = blockIdx.z ? d_hs : d_hf;
    __shared__ __align__(16) float As[32 * 68];
    __shared__ __align__(16) float Bs[32 * 132];
    int t = threadIdx.x, tx = t & 15, ty = t >> 4;
    int rowbase = blockIdx.x * 64;
    float acc[4][8];
#pragma unroll
    for (int ri = 0; ri < 4; ri++)
#pragma unroll
        for (int ci = 0; ci < 8; ci++) acc[ri][ci] = 0.f;

    for (int kc = 0; kc < 4; kc++) {
        __syncthreads();
#pragma unroll
        for (int j = 0; j < 2; j++) {
            int idx = t + j * 256;
            int r = idx >> 3, k4 = idx & 7;
            float4 v = *(const float4*)&x[(rowbase + r) * FDIM + kc * 32 + k4 * 4];
            As[(k4 * 4 + 0) * 68 + r] = v.x; As[(k4 * 4 + 1) * 68 + r] = v.y;
            As[(k4 * 4 + 2) * 68 + r] = v.z; As[(k4 * 4 + 3) * 68 + r] = v.w;
        }
#pragma unroll
        for (int j = 0; j < 4; j++) {
            int idx = t + j * 256;
            int kk = idx >> 5, c4 = idx & 31;
            *(float4*)&Bs[kk * 132 + c4 * 4] = *(const float4*)&W[(kc * 32 + kk) * FDIM + c4 * 4];
        }
        __syncthreads();
#pragma unroll 8
        for (int k = 0; k < 32; k++) {
            float4 a  = *(const float4*)&As[k * 68 + ty * 4];
            float4 b0 = *(const float4*)&Bs[k * 132 + tx * 8];
            float4 b1 = *(const float4*)&Bs[k * 132 + tx * 8 + 4];
            float av[4] = {a.x, a.y, a.z, a.w};
            float bv[8] = {b0.x, b0.y, b0.z, b0.w, b1.x, b1.y, b1.z, b1.w};
#pragma unroll
            for (int ri = 0; ri < 4; ri++)
#pragma unroll
                for (int ci = 0; ci < 8; ci++) acc[ri][ci] += av[ri] * bv[ci];
        }
    }
#pragma unroll
    for (int ri = 0; ri < 4; ri++) {
        int row = rowbase + ty * 4 + ri;
        float4 o0 = {acc[ri][0], acc[ri][1], acc[ri][2], acc[ri][3]};
        float4 o1 = {acc[ri][4], acc[ri][5], acc[ri][6], acc[ri][7]};
        *(float4*)&out[row * FDIM + tx * 8] = o0;
        *(float4*)&out[row * FDIM + tx * 8 + 4] = o1;
    }
}

// 9) GCN aggregate + bias + relu + layernorm (one warp per node)
__global__ void kagg(int which, const float* __restrict__ bias,
                     const float* __restrict__ gamma, const float* __restrict__ beta) {
    int d = (blockIdx.x * blockDim.x + threadIdx.x) >> 5;
    int lane = threadIdx.x & 31;
    const int* off = which ? d_offs : d_offf;
    const int* cnt = which ? d_cnts : d_cntf;
    const int* csr = which ? d_csrs : d_csrf;
    const float* dinv = which ? d_dinvs : d_dinvf;
    const float4* h4 = which ? (const float4*)d_hs : (const float4*)d_hf;
    float* outp = which ? d_stru : d_feat;

    int st = off[d], n = cnt[d];
    float dd = dinv[d];
    float ax = 0.f, ay = 0.f, az = 0.f, aw = 0.f;
    int e = 0;
    for (; e + 4 <= n; e += 4) {
        int s0 = csr[st+e], s1 = csr[st+e+1], s2 = csr[st+e+2], s3 = csr[st+e+3];
        float w0 = dinv[s0]*dd, w1 = dinv[s1]*dd, w2 = dinv[s2]*dd, w3 = dinv[s3]*dd;
        float4 v0 = h4[s0*32+lane], v1 = h4[s1*32+lane];
        float4 v2 = h4[s2*32+lane], v3 = h4[s3*32+lane];
        ax += v0.x*w0 + v1.x*w1 + v2.x*w2 + v3.x*w3;
        ay += v0.y*w0 + v1.y*w1 + v2.y*w2 + v3.y*w3;
        az += v0.z*w0 + v1.z*w1 + v2.z*w2 + v3.z*w3;
        aw += v0.w*w0 + v1.w*w1 + v2.w*w2 + v3.w*w3;
    }
    for (; e < n; e++) {
        int s = csr[st + e];
        float wg = dinv[s] * dd;
        float4 v = h4[s*32+lane];
        ax += v.x*wg; ay += v.y*wg; az += v.z*wg; aw += v.w*wg;
    }
    {
        float4 v = h4[d*32+lane];
        float wg = dd * dd;
        ax += v.x*wg; ay += v.y*wg; az += v.z*wg; aw += v.w*wg;
    }
    float4 b4 = ((const float4*)bias)[lane];
    ax = fmaxf(ax + b4.x, 0.f); ay = fmaxf(ay + b4.y, 0.f);
    az = fmaxf(az + b4.z, 0.f); aw = fmaxf(aw + b4.w, 0.f);
    float mean = warp_sum(ax + ay + az + aw) * (1.0f / 128.0f);
    float dx = ax - mean, dy = ay - mean, dz = az - mean, dw = aw - mean;
    float var = warp_sum(dx*dx + dy*dy + dz*dz + dw*dw) * (1.0f / 128.0f);
    float rs = rsqrtf(var + 1e-5f);
    float4 g4 = ((const float4*)gamma)[lane], e4 = ((const float4*)beta)[lane];
    float4 o = {dx*rs*g4.x + e4.x, dy*rs*g4.y + e4.y,
                dz*rs*g4.z + e4.z, dw*rs*g4.w + e4.w};
    ((float4*)outp)[d*32+lane] = o;
}

// 10) gate = sigmoid([feat|stru] @ W_gate + b_gate)
__global__ void __launch_bounds__(256) kgemm_gate(const float* __restrict__ Wg,
                                                  const float* __restrict__ bg) {
    __shared__ __align__(16) float As[32 * 68];
    __shared__ __align__(16) float Bs[32 * 132];
    int t = threadIdx.x, tx = t & 15, ty = t >> 4;
    int rowbase = blockIdx.x * 64;
    float acc[4][8];
#pragma unroll
    for (int ri = 0; ri < 4; ri++)
#pragma unroll
        for (int ci = 0; ci < 8; ci++) acc[ri][ci] = 0.f;

    for (int kc = 0; kc < 8; kc++) {
        const float* Asrc = (kc < 4) ? d_feat : d_stru;
        int kcol = (kc & 3) * 32;
        __syncthreads();
#pragma unroll
        for (int j = 0; j < 2; j++) {
            int idx = t + j * 256;
            int r = idx >> 3, k4 = idx & 7;
            float4 v = *(const float4*)&Asrc[(rowbase + r) * FDIM + kcol + k4 * 4];
            As[(k4 * 4 + 0) * 68 + r] = v.x; As[(k4 * 4 + 1) * 68 + r] = v.y;
            As[(k4 * 4 + 2) * 68 + r] = v.z; As[(k4 * 4 + 3) * 68 + r] = v.w;
        }
#pragma unroll
        for (int j = 0; j < 4; j++) {
            int idx = t + j * 256;
            int kk = idx >> 5, c4 = idx & 31;
            *(float4*)&Bs[kk * 132 + c4 * 4] = *(const float4*)&Wg[(kc * 32 + kk) * FDIM + c4 * 4];
        }
        __syncthreads();
#pragma unroll 8
        for (int k = 0; k < 32; k++) {
            float4 a  = *(const float4*)&As[k * 68 + ty * 4];
            float4 b0 = *(const float4*)&Bs[k * 132 + tx * 8];
            float4 b1 = *(const float4*)&Bs[k * 132 + tx * 8 + 4];
            float av[4] = {a.x, a.y, a.z, a.w};
            float bv[8] = {b0.x, b0.y, b0.z, b0.w, b1.x, b1.y, b1.z, b1.w};
#pragma unroll
            for (int ri = 0; ri < 4; ri++)
#pragma unroll
                for (int ci = 0; ci < 8; ci++) acc[ri][ci] += av[ri] * bv[ci];
        }
    }
    float bgv[8];
#pragma unroll
    for (int ci = 0; ci < 8; ci++) bgv[ci] = bg[tx * 8 + ci];
#pragma unroll
    for (int ri = 0; ri < 4; ri++) {
        int row = rowbase + ty * 4 + ri;
#pragma unroll
        for (int ci = 0; ci < 8; ci++) {
            float z = acc[ri][ci] + bgv[ci];
            d_gate[row * FDIM + tx * 8 + ci] = 1.0f / (1.0f + expf(-z));
        }
    }
}

// 11) fuse + layernorm + residual
__global__ void kfinal(const float* __restrict__ x, const float* __restrict__ gamma,
                       const float* __restrict__ beta, float* __restrict__ out) {
    int d = (blockIdx.x * blockDim.x + threadIdx.x) >> 5;
    int lane = threadIdx.x & 31;
    float4 f = ((const float4*)d_feat)[d*32+lane];
    float4 s = ((const float4*)d_stru)[d*32+lane];
    float4 g = ((const float4*)d_gate)[d*32+lane];
    float4 xv = ((const float4*)x)[d*32+lane];
    float fx = g.x*f.x + (1.f-g.x)*s.x;
    float fy = g.y*f.y + (1.f-g.y)*s.y;
    float fz = g.z*f.z + (1.f-g.z)*s.z;
    float fw = g.w*f.w + (1.f-g.w)*s.w;
    float mean = warp_sum(fx + fy + fz + fw) * (1.0f / 128.0f);
    float dx = fx-mean, dy = fy-mean, dz = fz-mean, dw = fw-mean;
    float var = warp_sum(dx*dx + dy*dy + dz*dz + dw*dw) * (1.0f / 128.0f);
    float rs = rsqrtf(var + 1e-5f);
    float4 g4 = ((const float4*)gamma)[lane], b4 = ((const float4*)beta)[lane];
    float4 o = {dx*rs*g4.x + b4.x + xv.x, dy*rs*g4.y + b4.y + xv.y,
                dz*rs*g4.z + b4.z + xv.z, dw*rs*g4.w + b4.w + xv.w};
    ((float4*)out)[d*32+lane] = o;
}

extern "C" void kernel_launch(void* const* d_in, const int* in_sizes, int n_in,
                              void* d_out, int out_size) {
    const float* x      = (const float*)d_in[0];
    const int*   ei     = (const int*)  d_in[1];
    const float* W_feat = (const float*)d_in[2];
    const float* b_feat = (const float*)d_in[3];
    const float* W_stru = (const float*)d_in[4];
    const float* b_stru = (const float*)d_in[5];
    const float* W_gate = (const float*)d_in[6];
    const float* b_gate = (const float*)d_in[7];
    const float* g_feat = (const float*)d_in[8];
    const float* be_feat= (const float*)d_in[9];
    const float* g_stru = (const float*)d_in[10];
    const float* be_stru= (const float*)d_in[11];
    const float* g_fus  = (const float*)d_in[12];
    const float* be_fus = (const float*)d_in[13];
    float* out = (float*)d_out;

    knorm<<<NUM, 128>>>(x);
    kinit<<<NUM / 256, 256>>>();
    kcnt_s<<<NE / 256, 256>>>(ei);
    ktopk<<<dim3(16, 64), 256>>>();
    kgemm_h<<<dim3(NUM / 64, 1, 2), 256>>>(x, W_feat, W_stru);
    kscan<<<1, 1024>>>(0);
    kscan<<<1, 1024>>>(1);
    kdinv<<<NUM / 256, 256>>>();
    kfill_f<<<(NUM * KSEL) / 256, 256>>>();
    kfill_s<<<NE / 256, 256>>>(ei);
    kagg<<<(NUM * 32) / 256, 256>>>(0, b_feat, g_feat, be_feat);
    kagg<<<(NUM * 32) / 256, 256>>>(1, b_stru, g_stru, be_stru);
    kgemm_gate<<<NUM / 64, 256>>>(W_gate, b_gate);
    kfinal<<<(NUM * 32) / 256, 256>>>(x, g_fus, be_fus, out);
}

// round 5
// speedup vs baseline: 1.3858x; 1.3858x over previous
#include <cuda_runtime.h>
#include <math.h>

#define BGRAPH 64
#define NNODE  1024
#define FDIM   128
#define NUM    (BGRAPH*NNODE)
#define NE     2097152
#define KSEL   4

__device__ float d_xn  [NUM*FDIM];
__device__ float d_hf  [NUM*FDIM];
__device__ float d_hs  [NUM*FDIM];
__device__ float d_feat[NUM*FDIM];
__device__ float d_stru[NUM*FDIM];
__device__ float d_gate[NUM*FDIM];
__device__ int   d_topk[NUM*KSEL];
__device__ int   d_cntf[NUM];
__device__ int   d_cnts[NUM];
__device__ int   d_offf[NUM];
__device__ int   d_offs[NUM];
__device__ int   d_fillf[NUM];
__device__ int   d_fills[NUM];
__device__ float d_dinvf[NUM];
__device__ float d_dinvs[NUM];
__device__ int   d_csrf[NUM*KSEL];
__device__ int   d_csrs[NE];

__device__ __forceinline__ float warp_sum(float v) {
#pragma unroll
    for (int o = 16; o > 0; o >>= 1) v += __shfl_xor_sync(0xffffffffu, v, o);
    return v;
}

__device__ __forceinline__ void ins4(unsigned long long& k0, unsigned long long& k1,
                                     unsigned long long& k2, unsigned long long& k3,
                                     unsigned long long c) {
    if (c < k3) {
        k3 = c;
        if (k3 < k2) { unsigned long long t = k2; k2 = k3; k3 = t; }
        if (k2 < k1) { unsigned long long t = k1; k1 = k2; k2 = t; }
        if (k1 < k0) { unsigned long long t = k0; k0 = k1; k1 = t; }
    }
}

// 1) row-normalize x
__global__ void knorm(const float* __restrict__ x) {
    int row = blockIdx.x, t = threadIdx.x;
    float v = x[row * FDIM + t];
    float ss = warp_sum(v * v);
    __shared__ float sh[4];
    if ((t & 31) == 0) sh[t >> 5] = ss;
    __syncthreads();
    float tot = sh[0] + sh[1] + sh[2] + sh[3];
    float den = fmaxf(sqrtf(tot), 1e-8f);
    d_xn[row * FDIM + t] = v / den;
}

// 2) zero counters
__global__ void kinit() {
    int i = blockIdx.x * blockDim.x + threadIdx.x;
    if (i < NUM) { d_cntf[i] = 0; d_cnts[i] = 0; d_fillf[i] = 0; d_fills[i] = 0; }
}

// 3) structural in-degree
__global__ void kcnt_s(const int* __restrict__ ei) {
    int e = blockIdx.x * blockDim.x + threadIdx.x;
    if (e < NE) atomicAdd(&d_cnts[ei[NE + e]], 1);
}

// 4) all-pairs cosine + top-4 farthest. grid(16,64), 256 thr; 64 rows x (8x128) cols.
// thread's 8 cols = {tx*4..tx*4+3, 64+tx*4..64+tx*4+3} -> conflict-free LDS.128
__global__ void __launch_bounds__(256) ktopk() {
    __shared__ __align__(16) float As[32 * 68];
    __shared__ __align__(16) float Bs[32 * 132];
    const int g = blockIdx.y;
    const int rowbase = blockIdx.x * 64;
    const int t = threadIdx.x, tx = t & 15, ty = t >> 4;
    const float* xg = d_xn + (size_t)g * NNODE * FDIM;

    unsigned long long tkA[4], tkB[4], tkC[4], tkD[4];
#pragma unroll
    for (int ri = 0; ri < 4; ri++) { tkA[ri]=tkB[ri]=tkC[ri]=tkD[ri]=0xffffffffffffffffull; }

    for (int cc = 0; cc < 8; cc++) {
        float acc[4][8];
#pragma unroll
        for (int ri = 0; ri < 4; ri++)
#pragma unroll
            for (int ci = 0; ci < 8; ci++) acc[ri][ci] = 0.f;

        for (int kc = 0; kc < 4; kc++) {
            __syncthreads();
#pragma unroll
            for (int j = 0; j < 2; j++) {
                int idx = t + j * 256;
                int r = idx >> 3, k4 = idx & 7;
                float4 v = *(const float4*)&xg[(rowbase + r) * FDIM + kc * 32 + k4 * 4];
                As[(k4 * 4 + 0) * 68 + r] = v.x; As[(k4 * 4 + 1) * 68 + r] = v.y;
                As[(k4 * 4 + 2) * 68 + r] = v.z; As[(k4 * 4 + 3) * 68 + r] = v.w;
            }
#pragma unroll
            for (int j = 0; j < 4; j++) {
                int idx = t + j * 256;
                int c = idx >> 3, k4 = idx & 7;
                float4 v = *(const float4*)&xg[(cc * 128 + c) * FDIM + kc * 32 + k4 * 4];
                Bs[(k4 * 4 + 0) * 132 + c] = v.x; Bs[(k4 * 4 + 1) * 132 + c] = v.y;
                Bs[(k4 * 4 + 2) * 132 + c] = v.z; Bs[(k4 * 4 + 3) * 132 + c] = v.w;
            }
            __syncthreads();
#pragma unroll 8
            for (int k = 0; k < 32; k++) {
                float4 a  = *(const float4*)&As[k * 68 + ty * 4];
                float4 b0 = *(const float4*)&Bs[k * 132 + tx * 4];
                float4 b1 = *(const float4*)&Bs[k * 132 + 64 + tx * 4];
                float av[4] = {a.x, a.y, a.z, a.w};
                float bv[8] = {b0.x, b0.y, b0.z, b0.w, b1.x, b1.y, b1.z, b1.w};
#pragma unroll
                for (int ri = 0; ri < 4; ri++)
#pragma unroll
                    for (int ci = 0; ci < 8; ci++) acc[ri][ci] += av[ri] * bv[ci];
            }
        }
#pragma unroll
        for (int ri = 0; ri < 4; ri++)
#pragma unroll
            for (int ci = 0; ci < 8; ci++) {
                int col = cc * 128 + ((ci < 4) ? (tx * 4 + ci) : (64 + tx * 4 + ci - 4));
                float dval = 1.0f - acc[ri][ci];
                unsigned u = __float_as_uint(dval);
                u = (u & 0x80000000u) ? ~u : (u | 0x80000000u);
                unsigned long long key =
                    (((unsigned long long)(~u)) << 10) | (unsigned long long)col;
                ins4(tkA[ri], tkB[ri], tkC[ri], tkD[ri], key);
            }
    }
#pragma unroll
    for (int off = 8; off > 0; off >>= 1) {
#pragma unroll
        for (int ri = 0; ri < 4; ri++) {
            unsigned long long c0 = __shfl_down_sync(0xffffffffu, tkA[ri], off, 16);
            unsigned long long c1 = __shfl_down_sync(0xffffffffu, tkB[ri], off, 16);
            unsigned long long c2 = __shfl_down_sync(0xffffffffu, tkC[ri], off, 16);
            unsigned long long c3 = __shfl_down_sync(0xffffffffu, tkD[ri], off, 16);
            if (tx < off) {
                ins4(tkA[ri], tkB[ri], tkC[ri], tkD[ri], c0);
                ins4(tkA[ri], tkB[ri], tkC[ri], tkD[ri], c1);
                ins4(tkA[ri], tkB[ri], tkC[ri], tkD[ri], c2);
                ins4(tkA[ri], tkB[ri], tkC[ri], tkD[ri], c3);
            }
        }
    }
    if (tx == 0) {
#pragma unroll
        for (int ri = 0; ri < 4; ri++) {
            int grow = g * NNODE + rowbase + ty * 4 + ri;
            unsigned long long ks[4] = {tkA[ri], tkB[ri], tkC[ri], tkD[ri]};
#pragma unroll
            for (int q = 0; q < 4; q++) {
                int j  = (int)(ks[q] & 1023ull);
                int dg = g * NNODE + j;
                d_topk[grow * 4 + q] = dg;
                atomicAdd(&d_cntf[dg], 1);
            }
        }
    }
}

// 5) exclusive scans (block 0 = feature counts, block 1 = structural)
__global__ void kscan() {
    int which = blockIdx.x;
    const int* cnt = which ? d_cnts : d_cntf;
    int* off = which ? d_offs : d_offf;
    __shared__ int sh[1024];
    int t = threadIdx.x;
    int base = t * 64;
    int sum = 0;
    for (int i = 0; i < 64; i++) sum += cnt[base + i];
    sh[t] = sum;
    __syncthreads();
    for (int o = 1; o < 1024; o <<= 1) {
        int v = (t >= o) ? sh[t - o] : 0;
        __syncthreads();
        sh[t] += v;
        __syncthreads();
    }
    int run = sh[t] - sum;
    for (int i = 0; i < 64; i++) { int c = cnt[base + i]; off[base + i] = run; run += c; }
}

// 6) dinv = rsqrt(deg) incl. self-loop
__global__ void kdinv() {
    int i = blockIdx.x * blockDim.x + threadIdx.x;
    if (i < NUM) {
        d_dinvf[i] = rsqrtf((float)(d_cntf[i] + 1));
        d_dinvs[i] = rsqrtf((float)(d_cnts[i] + 1));
    }
}

// 7) CSR fill
__global__ void kfill_f() {
    int e = blockIdx.x * blockDim.x + threadIdx.x;
    if (e < NUM * KSEL) {
        int srcn = e >> 2;
        int dg = d_topk[e];
        int pos = d_offf[dg] + atomicAdd(&d_fillf[dg], 1);
        d_csrf[pos] = srcn;
    }
}
__global__ void kfill_s(const int* __restrict__ ei) {
    int e = blockIdx.x * blockDim.x + threadIdx.x;
    if (e < NE) {
        int s = ei[e], dg = ei[NE + e];
        int pos = d_offs[dg] + atomicAdd(&d_fills[dg], 1);
        d_csrs[pos] = s;
    }
}

// 8) h = x @ W (z: 0=feat, 1=stru)
__global__ void __launch_bounds__(256) kgemm_h(const float* __restrict__ x,
                                               const float* __restrict__ Wf,
                                               const float* __restrict__ Wst) {
    const float* W = blockIdx.z ? Wst : Wf;
    float* out = blockIdx.z ? d_hs : d_hf;
    __shared__ __align__(16) float As[32 * 68];
    __shared__ __align__(16) float Bs[32 * 132];
    int t = threadIdx.x, tx = t & 15, ty = t >> 4;
    int rowbase = blockIdx.x * 64;
    float acc[4][8];
#pragma unroll
    for (int ri = 0; ri < 4; ri++)
#pragma unroll
        for (int ci = 0; ci < 8; ci++) acc[ri][ci] = 0.f;

    for (int kc = 0; kc < 4; kc++) {
        __syncthreads();
#pragma unroll
        for (int j = 0; j < 2; j++) {
            int idx = t + j * 256;
            int r = idx >> 3, k4 = idx & 7;
            float4 v = *(const float4*)&x[(rowbase + r) * FDIM + kc * 32 + k4 * 4];
            As[(k4 * 4 + 0) * 68 + r] = v.x; As[(k4 * 4 + 1) * 68 + r] = v.y;
            As[(k4 * 4 + 2) * 68 + r] = v.z; As[(k4 * 4 + 3) * 68 + r] = v.w;
        }
#pragma unroll
        for (int j = 0; j < 4; j++) {
            int idx = t + j * 256;
            int kk = idx >> 5, c4 = idx & 31;
            *(float4*)&Bs[kk * 132 + c4 * 4] = *(const float4*)&W[(kc * 32 + kk) * FDIM + c4 * 4];
        }
        __syncthreads();
#pragma unroll 8
        for (int k = 0; k < 32; k++) {
            float4 a  = *(const float4*)&As[k * 68 + ty * 4];
            float4 b0 = *(const float4*)&Bs[k * 132 + tx * 4];
            float4 b1 = *(const float4*)&Bs[k * 132 + 64 + tx * 4];
            float av[4] = {a.x, a.y, a.z, a.w};
            float bv[8] = {b0.x, b0.y, b0.z, b0.w, b1.x, b1.y, b1.z, b1.w};
#pragma unroll
            for (int ri = 0; ri < 4; ri++)
#pragma unroll
                for (int ci = 0; ci < 8; ci++) acc[ri][ci] += av[ri] * bv[ci];
        }
    }
#pragma unroll
    for (int ri = 0; ri < 4; ri++) {
        int row = rowbase + ty * 4 + ri;
        float4 o0 = {acc[ri][0], acc[ri][1], acc[ri][2], acc[ri][3]};
        float4 o1 = {acc[ri][4], acc[ri][5], acc[ri][6], acc[ri][7]};
        *(float4*)&out[row * FDIM + tx * 4] = o0;
        *(float4*)&out[row * FDIM + 64 + tx * 4] = o1;
    }
}

// 9) GCN aggregate + bias + relu + layernorm (one warp per node)
__global__ void kagg(int which, const float* __restrict__ bias,
                     const float* __restrict__ gamma, const float* __restrict__ beta) {
    int d = (blockIdx.x * blockDim.x + threadIdx.x) >> 5;
    int lane = threadIdx.x & 31;
    const int* off = which ? d_offs : d_offf;
    const int* cnt = which ? d_cnts : d_cntf;
    const int* csr = which ? d_csrs : d_csrf;
    const float* dinv = which ? d_dinvs : d_dinvf;
    const float4* h4 = which ? (const float4*)d_hs : (const float4*)d_hf;
    float* outp = which ? d_stru : d_feat;

    int st = off[d], n = cnt[d];
    float dd = dinv[d];
    float ax = 0.f, ay = 0.f, az = 0.f, aw = 0.f;
    int e = 0;
    for (; e + 4 <= n; e += 4) {
        int s0 = csr[st+e], s1 = csr[st+e+1], s2 = csr[st+e+2], s3 = csr[st+e+3];
        float w0 = dinv[s0]*dd, w1 = dinv[s1]*dd, w2 = dinv[s2]*dd, w3 = dinv[s3]*dd;
        float4 v0 = h4[s0*32+lane], v1 = h4[s1*32+lane];
        float4 v2 = h4[s2*32+lane], v3 = h4[s3*32+lane];
        ax += v0.x*w0 + v1.x*w1 + v2.x*w2 + v3.x*w3;
        ay += v0.y*w0 + v1.y*w1 + v2.y*w2 + v3.y*w3;
        az += v0.z*w0 + v1.z*w1 + v2.z*w2 + v3.z*w3;
        aw += v0.w*w0 + v1.w*w1 + v2.w*w2 + v3.w*w3;
    }
    for (; e < n; e++) {
        int s = csr[st + e];
        float wg = dinv[s] * dd;
        float4 v = h4[s*32+lane];
        ax += v.x*wg; ay += v.y*wg; az += v.z*wg; aw += v.w*wg;
    }
    {
        float4 v = h4[d*32+lane];
        float wg = dd * dd;
        ax += v.x*wg; ay += v.y*wg; az += v.z*wg; aw += v.w*wg;
    }
    float4 b4 = ((const float4*)bias)[lane];
    ax = fmaxf(ax + b4.x, 0.f); ay = fmaxf(ay + b4.y, 0.f);
    az = fmaxf(az + b4.z, 0.f); aw = fmaxf(aw + b4.w, 0.f);
    float mean = warp_sum(ax + ay + az + aw) * (1.0f / 128.0f);
    float dx = ax - mean, dy = ay - mean, dz = az - mean, dw = aw - mean;
    float var = warp_sum(dx*dx + dy*dy + dz*dz + dw*dw) * (1.0f / 128.0f);
    float rs = rsqrtf(var + 1e-5f);
    float4 g4 = ((const float4*)gamma)[lane], e4 = ((const float4*)beta)[lane];
    float4 o = {dx*rs*g4.x + e4.x, dy*rs*g4.y + e4.y,
                dz*rs*g4.z + e4.z, dw*rs*g4.w + e4.w};
    ((float4*)outp)[d*32+lane] = o;
}

// 10) gate = sigmoid([feat|stru] @ W_gate + b_gate)
__global__ void __launch_bounds__(256) kgemm_gate(const float* __restrict__ Wg,
                                                  const float* __restrict__ bg) {
    __shared__ __align__(16) float As[32 * 68];
    __shared__ __align__(16) float Bs[32 * 132];
    int t = threadIdx.x, tx = t & 15, ty = t >> 4;
    int rowbase = blockIdx.x * 64;
    float acc[4][8];
#pragma unroll
    for (int ri = 0; ri < 4; ri++)
#pragma unroll
        for (int ci = 0; ci < 8; ci++) acc[ri][ci] = 0.f;

    for (int kc = 0; kc < 8; kc++) {
        const float* Asrc = (kc < 4) ? d_feat : d_stru;
        int kcol = (kc & 3) * 32;
        __syncthreads();
#pragma unroll
        for (int j = 0; j < 2; j++) {
            int idx = t + j * 256;
            int r = idx >> 3, k4 = idx & 7;
            float4 v = *(const float4*)&Asrc[(rowbase + r) * FDIM + kcol + k4 * 4];
            As[(k4 * 4 + 0) * 68 + r] = v.x; As[(k4 * 4 + 1) * 68 + r] = v.y;
            As[(k4 * 4 + 2) * 68 + r] = v.z; As[(k4 * 4 + 3) * 68 + r] = v.w;
        }
#pragma unroll
        for (int j = 0; j < 4; j++) {
            int idx = t + j * 256;
            int kk = idx >> 5, c4 = idx & 31;
            *(float4*)&Bs[kk * 132 + c4 * 4] = *(const float4*)&Wg[(kc * 32 + kk) * FDIM + c4 * 4];
        }
        __syncthreads();
#pragma unroll 8
        for (int k = 0; k < 32; k++) {
            float4 a  = *(const float4*)&As[k * 68 + ty * 4];
            float4 b0 = *(const float4*)&Bs[k * 132 + tx * 4];
            float4 b1 = *(const float4*)&Bs[k * 132 + 64 + tx * 4];
            float av[4] = {a.x, a.y, a.z, a.w};
            float bv[8] = {b0.x, b0.y, b0.z, b0.w, b1.x, b1.y, b1.z, b1.w};
#pragma unroll
            for (int ri = 0; ri < 4; ri++)
#pragma unroll
                for (int ci = 0; ci < 8; ci++) acc[ri][ci] += av[ri] * bv[ci];
        }
    }
    float bgv[8];
#pragma unroll
    for (int ci = 0; ci < 8; ci++)
        bgv[ci] = bg[(ci < 4) ? (tx * 4 + ci) : (64 + tx * 4 + ci - 4)];
#pragma unroll
    for (int ri = 0; ri < 4; ri++) {
        int row = rowbase + ty * 4 + ri;
#pragma unroll
        for (int ci = 0; ci < 8; ci++) {
            int col = (ci < 4) ? (tx * 4 + ci) : (64 + tx * 4 + ci - 4);
            float z = acc[ri][ci] + bgv[ci];
            d_gate[row * FDIM + col] = 1.0f / (1.0f + expf(-z));
        }
    }
}

// 11) fuse + layernorm + residual
__global__ void kfinal(const float* __restrict__ x, const float* __restrict__ gamma,
                       const float* __restrict__ beta, float* __restrict__ out) {
    int d = (blockIdx.x * blockDim.x + threadIdx.x) >> 5;
    int lane = threadIdx.x & 31;
    float4 f = ((const float4*)d_feat)[d*32+lane];
    float4 s = ((const float4*)d_stru)[d*32+lane];
    float4 g = ((const float4*)d_gate)[d*32+lane];
    float4 xv = ((const float4*)x)[d*32+lane];
    float fx = g.x*f.x + (1.f-g.x)*s.x;
    float fy = g.y*f.y + (1.f-g.y)*s.y;
    float fz = g.z*f.z + (1.f-g.z)*s.z;
    float fw = g.w*f.w + (1.f-g.w)*s.w;
    float mean = warp_sum(fx + fy + fz + fw) * (1.0f / 128.0f);
    float dx = fx-mean, dy = fy-mean, dz = fz-mean, dw = fw-mean;
    float var = warp_sum(dx*dx + dy*dy + dz*dz + dw*dw) * (1.0f / 128.0f);
    float rs = rsqrtf(var + 1e-5f);
    float4 g4 = ((const float4*)gamma)[lane], b4 = ((const float4*)beta)[lane];
    float4 o = {dx*rs*g4.x + b4.x + xv.x, dy*rs*g4.y + b4.y + xv.y,
                dz*rs*g4.z + b4.z + xv.z, dw*rs*g4.w + b4.w + xv.w};
    ((float4*)out)[d*32+lane] = o;
}

extern "C" void kernel_launch(void* const* d_in, const int* in_sizes, int n_in,
                              void* d_out, int out_size) {
    const float* x      = (const float*)d_in[0];
    const int*   ei     = (const int*)  d_in[1];
    const float* W_feat = (const float*)d_in[2];
    const float* b_feat = (const float*)d_in[3];
    const float* W_stru = (const float*)d_in[4];
    const float* b_stru = (const float*)d_in[5];
    const float* W_gate = (const float*)d_in[6];
    const float* b_gate = (const float*)d_in[7];
    const float* g_feat = (const float*)d_in[8];
    const float* be_feat= (const float*)d_in[9];
    const float* g_stru = (const float*)d_in[10];
    const float* be_stru= (const float*)d_in[11];
    const float* g_fus  = (const float*)d_in[12];
    const float* be_fus = (const float*)d_in[13];
    float* out = (float*)d_out;

    knorm<<<NUM, 128>>>(x);
    kinit<<<NUM / 256, 256>>>();
    kcnt_s<<<NE / 256, 256>>>(ei);
    ktopk<<<dim3(16, 64), 256>>>();
    kgemm_h<<<dim3(NUM / 64, 1, 2), 256>>>(x, W_feat, W_stru);
    kscan<<<2, 1024>>>();
    kdinv<<<NUM / 256, 256>>>();
    kfill_f<<<(NUM * KSEL) / 256, 256>>>();
    kfill_s<<<NE / 256, 256>>>(ei);
    kagg<<<(NUM * 32) / 256, 256>>>(0, b_feat, g_feat, be_feat);
    kagg<<<(NUM * 32) / 256, 256>>>(1, b_stru, g_stru, be_stru);
    kgemm_gate<<<NUM / 64, 256>>>(W_gate, b_gate);
    kfinal<<<(NUM * 32) / 256, 256>>>(x, g_fus, be_fus, out);
}